// round 6
// baseline (speedup 1.0000x reference)
#include <cuda_runtime.h>
#include <math.h>
#include <stdint.h>

// Problem constants (fixed by the dataset)
#define T_TOK 4096
#define HID   1024
#define NE    16
#define FE    512
#define FS    2048
#define NPAIR (T_TOK * 2)

// ---------------------------------------------------------------------------
// Scratch
// ---------------------------------------------------------------------------
__device__ float g_gate_s[(size_t)T_TOK * FS];   // gate, then inter (in-place)
__device__ float g_gate_r[(size_t)NPAIR * FE];   // routed gate, then inter
__device__ float g_routed[(size_t)NPAIR * HID];
__device__ int   g_cnt[NE];
__device__ int   g_bucket[NE * T_TOK];
__device__ float g_pw[NPAIR];

// ---------------------------------------------------------------------------
// Router (validated rounds 1-4)
// ---------------------------------------------------------------------------
__global__ void zero_counts_kernel() {
    if (threadIdx.x < NE) g_cnt[threadIdx.x] = 0;
}

__global__ void router_kernel(const float* __restrict__ x,
                              const float* __restrict__ rw) {
    int warp = threadIdx.x >> 5;
    int lane = threadIdx.x & 31;
    int t = blockIdx.x * (blockDim.x >> 5) + warp;
    if (t >= T_TOK) return;

    float acc[NE];
#pragma unroll
    for (int e = 0; e < NE; e++) acc[e] = 0.0f;

    const float* xr = x + (size_t)t * HID;
    for (int d = lane; d < HID; d += 32) {
        float xv = xr[d];
        const float* r = rw + (size_t)d * NE;
#pragma unroll
        for (int e = 0; e < NE; e++) acc[e] = fmaf(xv, r[e], acc[e]);
    }
#pragma unroll
    for (int e = 0; e < NE; e++) {
#pragma unroll
        for (int off = 16; off; off >>= 1)
            acc[e] += __shfl_xor_sync(0xffffffffu, acc[e], off);
    }

    if (lane == 0) {
        float mx = acc[0];
#pragma unroll
        for (int e = 1; e < NE; e++) mx = fmaxf(mx, acc[e]);
        float p[NE];
        float s = 0.0f;
#pragma unroll
        for (int e = 0; e < NE; e++) { p[e] = expf(acc[e] - mx); s += p[e]; }
        float inv = 1.0f / s;
#pragma unroll
        for (int e = 0; e < NE; e++) p[e] *= inv;

        int   i0 = 0; float w0 = p[0];
#pragma unroll
        for (int e = 1; e < NE; e++) if (p[e] > w0) { w0 = p[e]; i0 = e; }
        int   i1 = -1; float w1 = -1.0f;
#pragma unroll
        for (int e = 0; e < NE; e++)
            if (e != i0 && p[e] > w1) { w1 = p[e]; i1 = e; }

        int pos0 = atomicAdd(&g_cnt[i0], 1);
        g_bucket[i0 * T_TOK + pos0] = 2 * t;
        int pos1 = atomicAdd(&g_cnt[i1], 1);
        g_bucket[i1 * T_TOK + pos1] = 2 * t + 1;
        g_pw[2 * t]     = w0;
        g_pw[2 * t + 1] = w1;
    }
}

// ---------------------------------------------------------------------------
// 3xTF32 split + mma.sync wrapper (validated)
// ---------------------------------------------------------------------------
__device__ __forceinline__ void split_tf32(float v, uint32_t& hi, uint32_t& lo) {
    uint32_t h;
    asm("cvt.rna.tf32.f32 %0, %1;" : "=r"(h) : "f"(v));
    float r = v - __uint_as_float(h);
    uint32_t l;
    asm("cvt.rna.tf32.f32 %0, %1;" : "=r"(l) : "f"(r));
    hi = h; lo = l;
}

__device__ __forceinline__ void mma_tf32(float* d,
                                         const uint32_t* a,
                                         const uint32_t* b) {
    asm volatile(
        "mma.sync.aligned.m16n8k8.row.col.f32.tf32.tf32.f32 "
        "{%0,%1,%2,%3}, {%4,%5,%6,%7}, {%8,%9}, {%0,%1,%2,%3};\n"
        : "+f"(d[0]), "+f"(d[1]), "+f"(d[2]), "+f"(d[3])
        : "r"(a[0]), "r"(a[1]), "r"(a[2]), "r"(a[3]),
          "r"(b[0]), "r"(b[1]));
}

// ---------------------------------------------------------------------------
// Tensor GEMM 128x128x16, 256 threads, producer-split, LDS.64 fragments.
//
// Smem word layouts (per stage):
//   A: word(m,k) = m*24 + (k>>3)*8 + (k&3)*2 + ((k>>2)&1)     [pairs (k,k+4)]
//      Ah at 0 (3072 w), Al at 3072
//   B: word(k,c) = kp*264 + c*2 + slot, kp=(k&3)+4*(k>>3), slot=(k>>2)&1
//      Bh at 6144 (2112 w), Bl at 8256
//   stage stride 10368 words (41472 B), 2 stages = 82944 B
//
// MODE 0: plain. MODE 1: gather x rows by pair>>1, scatter C by pair.
// MODE 2: gather rows by pair, scale C by router weight, scatter by pair.
// FUSE 1: C[..] = silu(G[..]) * acc  (G indexed identically to C).
// ---------------------------------------------------------------------------
#define BM 128
#define BN 128
#define BK 16
#define A_STRIDE 24
#define B_STRIDE 264
#define OFF_AL 3072
#define OFF_BH 6144
#define OFF_BL 8256
#define STAGEF 10368
#define SMEM_DYN (2 * STAGEF * 4)

template <int MODE, int FUSE>
__global__ __launch_bounds__(256, 2)
void tgemm_kernel(const float* __restrict__ A,
                  const float* __restrict__ B,
                  float* __restrict__ C,
                  const float* __restrict__ G,
                  int M, int N, int K) {
    int e = blockIdx.z;
    int m_rows = M;
    const int* rowlist = nullptr;
    if (MODE != 0) {
        m_rows  = g_cnt[e];
        rowlist = g_bucket + e * T_TOK;
        B += (size_t)e * K * N;
    }
    const int m0 = blockIdx.y * BM;
    const int n0 = blockIdx.x * BN;
    if (m0 >= m_rows) return;

    extern __shared__ uint32_t sm[];

    const int tid  = threadIdx.x;
    const int lane = tid & 31;
    const int wid  = tid >> 5;
    const int warp_m = wid >> 2;          // 0..1
    const int warp_n = wid & 3;           // 0..3
    const int g  = lane >> 2;             // 0..7
    const int t4 = lane & 3;              // 0..3
    const int mb = warp_m * 64;
    const int nb = warp_n * 32;

    // --- loader mappings ---
    // A: m = tid>>1, k-octet base akq = (tid&1)*8
    const int am  = tid >> 1;
    const int akq = (tid & 1) * 8;
    // B: p = tid>>5 -> rows r0=(p&3)+((p>>2)<<3), r1=r0+4 (a k-pair);
    //    kp row in smem = (p&3)+4*(p>>2); cols c0+32i, c0 = tid&31
    const int bp  = tid >> 5;
    const int br0 = (bp & 3) + ((bp >> 2) << 3);
    const int bkp = (bp & 3) + 4 * (bp >> 2);
    const int bc0 = tid & 31;

    const int  ar_g = m0 + am;
    const bool av   = ar_g < m_rows;
    const int  aidx = av ? ar_g : 0;
    const float* Arow;
    if (MODE == 0)      Arow = A + (size_t)aidx * K;
    else if (MODE == 1) Arow = A + (size_t)(rowlist[aidx] >> 1) * K;
    else                Arow = A + (size_t)rowlist[aidx] * K;

    const float* B0 = B + (size_t)br0 * N + n0 + bc0;        // row r0
    const float* B1 = B + (size_t)(br0 + 4) * N + n0 + bc0;  // row r0+4

    // store one stage from registers
    auto stage_store = [&](int s, const float* va, const float* vb0,
                           const float* vb1) {
        uint32_t* st = sm + s * STAGEF;
        uint32_t* stA = st + am * A_STRIDE + (akq >> 3) * 8;
#pragma unroll
        for (int i = 0; i < 4; i++) {
            uint32_t h0, l0, h1, l1;
            split_tf32(va[i], h0, l0);
            split_tf32(va[i + 4], h1, l1);
            *(uint2*)(stA + 2 * i)          = make_uint2(h0, h1);
            *(uint2*)(stA + OFF_AL + 2 * i) = make_uint2(l0, l1);
        }
        uint32_t* stB = st + OFF_BH + bkp * B_STRIDE + bc0 * 2;
#pragma unroll
        for (int i = 0; i < 4; i++) {
            uint32_t h0, l0, h1, l1;
            split_tf32(vb0[i], h0, l0);
            split_tf32(vb1[i], h1, l1);
            *(uint2*)(stB + 64 * i)                       = make_uint2(h0, h1);
            *(uint2*)(stB + (OFF_BL - OFF_BH) + 64 * i)   = make_uint2(l0, l1);
        }
    };

    // Prefetch stage 0
    float va[8], vb0[4], vb1[4];
    {
#pragma unroll
        for (int i = 0; i < 8; i++) va[i] = av ? Arow[akq + i] : 0.0f;
#pragma unroll
        for (int i = 0; i < 4; i++) {
            vb0[i] = B0[32 * i];
            vb1[i] = B1[32 * i];
        }
        stage_store(0, va, vb0, vb1);
    }
    __syncthreads();

    float acc[4][4][4];
#pragma unroll
    for (int i = 0; i < 4; i++)
#pragma unroll
        for (int j = 0; j < 4; j++)
#pragma unroll
            for (int r = 0; r < 4; r++) acc[i][j][r] = 0.0f;

    const int KT = K / BK;

    for (int kt = 0; kt < KT; kt++) {
        const int cur = kt & 1;
        if (kt + 1 < KT) {
            const int k0 = (kt + 1) * BK;
#pragma unroll
            for (int i = 0; i < 8; i++) va[i] = av ? Arow[k0 + akq + i] : 0.0f;
#pragma unroll
            for (int i = 0; i < 4; i++) {
                vb0[i] = B0[(size_t)k0 * N + 32 * i];
                vb1[i] = B1[(size_t)k0 * N + 32 * i];
            }
        }

        const uint32_t* Ah = sm + cur * STAGEF;
        const uint32_t* Bh = Ah + OFF_BH;

#pragma unroll
        for (int kk = 0; kk < BK; kk += 8) {
            const int kg = kk >> 3;
            uint32_t bh[4][2], bl[4][2];
#pragma unroll
            for (int nt = 0; nt < 4; nt++) {
                const int col = nb + nt * 8 + g;
                const uint32_t* bptr = Bh + (t4 + 4 * kg) * B_STRIDE + col * 2;
                uint2 h = *(const uint2*)bptr;
                uint2 l = *(const uint2*)(bptr + (OFF_BL - OFF_BH));
                bh[nt][0] = h.x; bh[nt][1] = h.y;
                bl[nt][0] = l.x; bl[nt][1] = l.y;
            }
#pragma unroll
            for (int mt = 0; mt < 4; mt++) {
                const int r0w = (mb + mt * 16 + g) * A_STRIDE + kg * 8 + 2 * t4;
                uint2 p0 = *(const uint2*)(Ah + r0w);
                uint2 p1 = *(const uint2*)(Ah + r0w + 8 * A_STRIDE);
                uint2 q0 = *(const uint2*)(Ah + OFF_AL + r0w);
                uint2 q1 = *(const uint2*)(Ah + OFF_AL + r0w + 8 * A_STRIDE);
                uint32_t ah[4] = {p0.x, p1.x, p0.y, p1.y};
                uint32_t al[4] = {q0.x, q1.x, q0.y, q1.y};
#pragma unroll
                for (int nt = 0; nt < 4; nt++) {
                    mma_tf32(acc[mt][nt], ah, bh[nt]);
                    mma_tf32(acc[mt][nt], ah, bl[nt]);
                    mma_tf32(acc[mt][nt], al, bh[nt]);
                }
            }
        }

        if (kt + 1 < KT) stage_store(cur ^ 1, va, vb0, vb1);
        __syncthreads();
    }

    // Epilogue
#pragma unroll
    for (int mt = 0; mt < 4; mt++) {
        const int r0 = m0 + mb + mt * 16 + g;
        const int r1 = r0 + 8;
        float* Crow0 = nullptr; float* Crow1 = nullptr;
        const float* Grow0 = nullptr; const float* Grow1 = nullptr;
        float s0 = 1.0f, s1 = 1.0f;
        if (r0 < m_rows) {
            size_t ro;
            if (MODE == 0) ro = (size_t)r0 * N;
            else {
                const int p = rowlist[r0];
                ro = (size_t)p * N;
                if (MODE == 2) s0 = g_pw[p];
            }
            Crow0 = C + ro;
            if (FUSE) Grow0 = G + ro;
        }
        if (r1 < m_rows) {
            size_t ro;
            if (MODE == 0) ro = (size_t)r1 * N;
            else {
                const int p = rowlist[r1];
                ro = (size_t)p * N;
                if (MODE == 2) s1 = g_pw[p];
            }
            Crow1 = C + ro;
            if (FUSE) Grow1 = G + ro;
        }
#pragma unroll
        for (int nt = 0; nt < 4; nt++) {
            const int c = n0 + nb + nt * 8 + 2 * t4;
            if (Crow0) {
                float o0 = acc[mt][nt][0] * s0, o1 = acc[mt][nt][1] * s0;
                if (FUSE) {
                    float2 gv = *(const float2*)(Grow0 + c);
                    o0 *= gv.x / (1.0f + expf(-gv.x));
                    o1 *= gv.y / (1.0f + expf(-gv.y));
                }
                *(float2*)(Crow0 + c) = make_float2(o0, o1);
            }
            if (Crow1) {
                float o0 = acc[mt][nt][2] * s1, o1 = acc[mt][nt][3] * s1;
                if (FUSE) {
                    float2 gv = *(const float2*)(Grow1 + c);
                    o0 *= gv.x / (1.0f + expf(-gv.x));
                    o1 *= gv.y / (1.0f + expf(-gv.y));
                }
                *(float2*)(Crow1 + c) = make_float2(o0, o1);
            }
        }
    }
}

// ---------------------------------------------------------------------------
// Final: out[t] += routed[2t] + routed[2t+1]
// ---------------------------------------------------------------------------
__global__ void final_add_kernel(float* __restrict__ out) {
    int i = blockIdx.x * blockDim.x + threadIdx.x;
    if (i >= T_TOK * HID / 4) return;
    const int t  = i >> 8;
    const int d4 = i & 255;
    float4 o = ((const float4*)out)[i];
    float4 a = ((const float4*)(g_routed + (size_t)(2 * t) * HID))[d4];
    float4 b = ((const float4*)(g_routed + (size_t)(2 * t + 1) * HID))[d4];
    o.x += a.x + b.x;
    o.y += a.y + b.y;
    o.z += a.z + b.z;
    o.w += a.w + b.w;
    ((float4*)out)[i] = o;
}

// ---------------------------------------------------------------------------
// Launch
// ---------------------------------------------------------------------------
extern "C" void kernel_launch(void* const* d_in, const int* in_sizes, int n_in,
                              void* d_out, int out_size) {
    const float* x  = (const float*)d_in[0];
    const float* rw = (const float*)d_in[1];
    const float* eg = (const float*)d_in[2];
    const float* eu = (const float*)d_in[3];
    const float* ed = (const float*)d_in[4];
    const float* sg = (const float*)d_in[5];
    const float* su = (const float*)d_in[6];
    const float* sd = (const float*)d_in[7];
    float* out = (float*)d_out;

    void *p_gate_s, *p_gate_r, *p_routed;
    cudaGetSymbolAddress(&p_gate_s, g_gate_s);
    cudaGetSymbolAddress(&p_gate_r, g_gate_r);
    cudaGetSymbolAddress(&p_routed, g_routed);

    cudaFuncSetAttribute(tgemm_kernel<0, 0>,
                         cudaFuncAttributeMaxDynamicSharedMemorySize, SMEM_DYN);
    cudaFuncSetAttribute(tgemm_kernel<0, 1>,
                         cudaFuncAttributeMaxDynamicSharedMemorySize, SMEM_DYN);
    cudaFuncSetAttribute(tgemm_kernel<1, 0>,
                         cudaFuncAttributeMaxDynamicSharedMemorySize, SMEM_DYN);
    cudaFuncSetAttribute(tgemm_kernel<1, 1>,
                         cudaFuncAttributeMaxDynamicSharedMemorySize, SMEM_DYN);
    cudaFuncSetAttribute(tgemm_kernel<2, 0>,
                         cudaFuncAttributeMaxDynamicSharedMemorySize, SMEM_DYN);

    zero_counts_kernel<<<1, 32>>>();
    router_kernel<<<T_TOK / 4, 128>>>(x, rw);

    // Shared expert: gate -> (up * silu fused) -> down
    tgemm_kernel<0, 0><<<dim3(FS / BN, T_TOK / BM, 1), 256, SMEM_DYN>>>(
        x, sg, (float*)p_gate_s, nullptr, T_TOK, FS, HID);
    tgemm_kernel<0, 1><<<dim3(FS / BN, T_TOK / BM, 1), 256, SMEM_DYN>>>(
        x, su, (float*)p_gate_s, (const float*)p_gate_s, T_TOK, FS, HID);
    tgemm_kernel<0, 0><<<dim3(HID / BN, T_TOK / BM, 1), 256, SMEM_DYN>>>(
        (const float*)p_gate_s, sd, out, nullptr, T_TOK, HID, FS);

    // Routed experts: gate -> (up * silu fused) -> down (scaled scatter)
    tgemm_kernel<1, 0><<<dim3(FE / BN, T_TOK / BM, NE), 256, SMEM_DYN>>>(
        x, eg, (float*)p_gate_r, nullptr, 0, FE, HID);
    tgemm_kernel<1, 1><<<dim3(FE / BN, T_TOK / BM, NE), 256, SMEM_DYN>>>(
        x, eu, (float*)p_gate_r, (const float*)p_gate_r, 0, FE, HID);
    tgemm_kernel<2, 0><<<dim3(HID / BN, T_TOK / BM, NE), 256, SMEM_DYN>>>(
        (const float*)p_gate_r, ed, (float*)p_routed, nullptr, 0, HID, FE);

    final_add_kernel<<<(T_TOK * HID / 4) / 256, 256>>>(out);
}

// round 7
// speedup vs baseline: 1.2142x; 1.2142x over previous
#include <cuda_runtime.h>
#include <math.h>
#include <stdint.h>

// Problem constants (fixed by the dataset)
#define T_TOK 4096
#define HID   1024
#define NE    16
#define FE    512
#define FS    2048
#define NPAIR (T_TOK * 2)

// ---------------------------------------------------------------------------
// Scratch
// ---------------------------------------------------------------------------
__device__ float g_gate_s[(size_t)T_TOK * FS];   // gate, then inter (in-place)
__device__ float g_gate_r[(size_t)NPAIR * FE];   // routed gate, then inter
__device__ float g_routed[(size_t)NPAIR * HID];
__device__ int   g_cnt[NE];
__device__ int   g_bucket[NE * T_TOK];
__device__ float g_pw[NPAIR];

// ---------------------------------------------------------------------------
// Router (validated rounds 1-6)
// ---------------------------------------------------------------------------
__global__ void zero_counts_kernel() {
    if (threadIdx.x < NE) g_cnt[threadIdx.x] = 0;
}

__global__ void router_kernel(const float* __restrict__ x,
                              const float* __restrict__ rw) {
    int warp = threadIdx.x >> 5;
    int lane = threadIdx.x & 31;
    int t = blockIdx.x * (blockDim.x >> 5) + warp;
    if (t >= T_TOK) return;

    float acc[NE];
#pragma unroll
    for (int e = 0; e < NE; e++) acc[e] = 0.0f;

    const float* xr = x + (size_t)t * HID;
    for (int d = lane; d < HID; d += 32) {
        float xv = xr[d];
        const float* r = rw + (size_t)d * NE;
#pragma unroll
        for (int e = 0; e < NE; e++) acc[e] = fmaf(xv, r[e], acc[e]);
    }
#pragma unroll
    for (int e = 0; e < NE; e++) {
#pragma unroll
        for (int off = 16; off; off >>= 1)
            acc[e] += __shfl_xor_sync(0xffffffffu, acc[e], off);
    }

    if (lane == 0) {
        float mx = acc[0];
#pragma unroll
        for (int e = 1; e < NE; e++) mx = fmaxf(mx, acc[e]);
        float p[NE];
        float s = 0.0f;
#pragma unroll
        for (int e = 0; e < NE; e++) { p[e] = expf(acc[e] - mx); s += p[e]; }
        float inv = 1.0f / s;
#pragma unroll
        for (int e = 0; e < NE; e++) p[e] *= inv;

        int   i0 = 0; float w0 = p[0];
#pragma unroll
        for (int e = 1; e < NE; e++) if (p[e] > w0) { w0 = p[e]; i0 = e; }
        int   i1 = -1; float w1 = -1.0f;
#pragma unroll
        for (int e = 0; e < NE; e++)
            if (e != i0 && p[e] > w1) { w1 = p[e]; i1 = e; }

        int pos0 = atomicAdd(&g_cnt[i0], 1);
        g_bucket[i0 * T_TOK + pos0] = 2 * t;
        int pos1 = atomicAdd(&g_cnt[i1], 1);
        g_bucket[i1 * T_TOK + pos1] = 2 * t + 1;
        g_pw[2 * t]     = w0;
        g_pw[2 * t + 1] = w1;
    }
}

// ---------------------------------------------------------------------------
// 3xTF32 split + mma.sync wrapper (validated)
// ---------------------------------------------------------------------------
__device__ __forceinline__ void split_tf32(float v, uint32_t& hi, uint32_t& lo) {
    uint32_t h;
    asm("cvt.rna.tf32.f32 %0, %1;" : "=r"(h) : "f"(v));
    float r = v - __uint_as_float(h);
    uint32_t l;
    asm("cvt.rna.tf32.f32 %0, %1;" : "=r"(l) : "f"(r));
    hi = h; lo = l;
}

__device__ __forceinline__ void mma_tf32(float* d,
                                         const uint32_t* a,
                                         const uint32_t* b) {
    asm volatile(
        "mma.sync.aligned.m16n8k8.row.col.f32.tf32.tf32.f32 "
        "{%0,%1,%2,%3}, {%4,%5,%6,%7}, {%8,%9}, {%0,%1,%2,%3};\n"
        : "+f"(d[0]), "+f"(d[1]), "+f"(d[2]), "+f"(d[3])
        : "r"(a[0]), "r"(a[1]), "r"(a[2]), "r"(a[3]),
          "r"(b[0]), "r"(b[1]));
}

// ---------------------------------------------------------------------------
// Tensor GEMM 128x128x16, 256 threads, producer-side hi/lo split.
// ROUND-4 smem layout (validated: tensor 53.7%, no conflicts):
//   Ah: [128][20] off 0, Al: off 2560, Bh: [16][136] off 5120, Bl: off 7296
//   stage stride 9472 words, 2 stages.
// MODE 0: plain. MODE 1: gather x rows by pair>>1, scatter C by pair.
// MODE 2: gather rows by pair, scale C by router weight, scatter by pair.
// FUSE 1: C[..] = silu(G[..]) * acc  (G indexed identically to C).
// ---------------------------------------------------------------------------
#define BM 128
#define BN 128
#define BK 16
#define A_PAD 20
#define B_PAD 136
#define OFF_AL 2560
#define OFF_BH 5120
#define OFF_BL 7296
#define STAGEF 9472
#define SMEM_DYN (2 * STAGEF * 4)

template <int MODE, int FUSE>
__global__ __launch_bounds__(256, 2)
void tgemm_kernel(const float* __restrict__ A,
                  const float* __restrict__ B,
                  float* __restrict__ C,
                  const float* __restrict__ G,
                  int M, int N, int K) {
    int e = blockIdx.z;
    int m_rows = M;
    const int* rowlist = nullptr;
    if (MODE != 0) {
        m_rows  = g_cnt[e];
        rowlist = g_bucket + e * T_TOK;
        B += (size_t)e * K * N;
    }
    const int m0 = blockIdx.y * BM;
    const int n0 = blockIdx.x * BN;
    if (m0 >= m_rows) return;

    extern __shared__ uint32_t sm[];

    const int tid  = threadIdx.x;
    const int lane = tid & 31;
    const int wid  = tid >> 5;
    const int warp_m = wid >> 2;          // 0..1
    const int warp_n = wid & 3;           // 0..3
    const int g  = lane >> 2;             // 0..7
    const int t4 = lane & 3;              // 0..3
    const int mb = warp_m * 64;
    const int nb = warp_n * 32;

    // --- loader mappings (round 4, validated) ---
    const int am  = tid >> 1;
    const int akq = (tid & 1) * 8;
    const int bkr = tid >> 5;
    const int bn4 = (tid & 31) * 4;

    const int  ar_g = m0 + am;
    const bool av   = ar_g < m_rows;
    const int  aidx = av ? ar_g : 0;
    const float* Arow;
    if (MODE == 0)      Arow = A + (size_t)aidx * K;
    else if (MODE == 1) Arow = A + (size_t)(rowlist[aidx] >> 1) * K;
    else                Arow = A + (size_t)rowlist[aidx] * K;

    const float* Bp0 = B + (size_t)bkr * N + n0 + bn4;
    const float* Bp1 = B + (size_t)(bkr + 8) * N + n0 + bn4;

    auto stage_store = [&](int s, float4 va0, float4 va1, float4 vb0, float4 vb1) {
        uint32_t* st = sm + s * STAGEF;
        uint32_t h0, l0, h1, l1, h2, l2, h3, l3;
        split_tf32(va0.x, h0, l0); split_tf32(va0.y, h1, l1);
        split_tf32(va0.z, h2, l2); split_tf32(va0.w, h3, l3);
        *(uint4*)(st + am * A_PAD + akq)          = make_uint4(h0, h1, h2, h3);
        *(uint4*)(st + OFF_AL + am * A_PAD + akq) = make_uint4(l0, l1, l2, l3);
        split_tf32(va1.x, h0, l0); split_tf32(va1.y, h1, l1);
        split_tf32(va1.z, h2, l2); split_tf32(va1.w, h3, l3);
        *(uint4*)(st + am * A_PAD + akq + 4)          = make_uint4(h0, h1, h2, h3);
        *(uint4*)(st + OFF_AL + am * A_PAD + akq + 4) = make_uint4(l0, l1, l2, l3);
        split_tf32(vb0.x, h0, l0); split_tf32(vb0.y, h1, l1);
        split_tf32(vb0.z, h2, l2); split_tf32(vb0.w, h3, l3);
        *(uint4*)(st + OFF_BH + bkr * B_PAD + bn4) = make_uint4(h0, h1, h2, h3);
        *(uint4*)(st + OFF_BL + bkr * B_PAD + bn4) = make_uint4(l0, l1, l2, l3);
        split_tf32(vb1.x, h0, l0); split_tf32(vb1.y, h1, l1);
        split_tf32(vb1.z, h2, l2); split_tf32(vb1.w, h3, l3);
        *(uint4*)(st + OFF_BH + (bkr + 8) * B_PAD + bn4) = make_uint4(h0, h1, h2, h3);
        *(uint4*)(st + OFF_BL + (bkr + 8) * B_PAD + bn4) = make_uint4(l0, l1, l2, l3);
    };

    // Prefetch stage 0
    {
        float4 va0 = make_float4(0, 0, 0, 0), va1 = va0;
        if (av) {
            va0 = *(const float4*)(Arow + akq);
            va1 = *(const float4*)(Arow + akq + 4);
        }
        float4 vb0 = *(const float4*)Bp0;
        float4 vb1 = *(const float4*)Bp1;
        stage_store(0, va0, va1, vb0, vb1);
    }
    __syncthreads();

    float acc[4][4][4];
#pragma unroll
    for (int i = 0; i < 4; i++)
#pragma unroll
        for (int j = 0; j < 4; j++)
#pragma unroll
            for (int r = 0; r < 4; r++) acc[i][j][r] = 0.0f;

    const int KT = K / BK;
    float4 va0, va1, vb0, vb1;

    for (int kt = 0; kt < KT; kt++) {
        const int cur = kt & 1;
        if (kt + 1 < KT) {
            const int k0 = (kt + 1) * BK;
            va0 = make_float4(0, 0, 0, 0); va1 = va0;
            if (av) {
                va0 = *(const float4*)(Arow + k0 + akq);
                va1 = *(const float4*)(Arow + k0 + akq + 4);
            }
            vb0 = *(const float4*)(Bp0 + (size_t)k0 * N);
            vb1 = *(const float4*)(Bp1 + (size_t)k0 * N);
        }

        const uint32_t* Ah = sm + cur * STAGEF;
        const uint32_t* Al = Ah + OFF_AL;
        const uint32_t* Bh = sm + cur * STAGEF + OFF_BH;
        const uint32_t* Bl = Bh + (OFF_BL - OFF_BH);

#pragma unroll
        for (int kk = 0; kk < BK; kk += 8) {
            uint32_t bh[4][2], bl[4][2];
#pragma unroll
            for (int nt = 0; nt < 4; nt++) {
                const int col = nb + nt * 8 + g;
                bh[nt][0] = Bh[(kk + t4) * B_PAD + col];
                bh[nt][1] = Bh[(kk + t4 + 4) * B_PAD + col];
                bl[nt][0] = Bl[(kk + t4) * B_PAD + col];
                bl[nt][1] = Bl[(kk + t4 + 4) * B_PAD + col];
            }
#pragma unroll
            for (int mt = 0; mt < 4; mt++) {
                const int r0 = (mb + mt * 16 + g) * A_PAD;
                const int r1 = r0 + 8 * A_PAD;
                uint32_t ah[4], al[4];
                ah[0] = Ah[r0 + kk + t4];
                ah[1] = Ah[r1 + kk + t4];
                ah[2] = Ah[r0 + kk + t4 + 4];
                ah[3] = Ah[r1 + kk + t4 + 4];
                al[0] = Al[r0 + kk + t4];
                al[1] = Al[r1 + kk + t4];
                al[2] = Al[r0 + kk + t4 + 4];
                al[3] = Al[r1 + kk + t4 + 4];
#pragma unroll
                for (int nt = 0; nt < 4; nt++) {
                    mma_tf32(acc[mt][nt], ah, bh[nt]);
                    mma_tf32(acc[mt][nt], ah, bl[nt]);
                    mma_tf32(acc[mt][nt], al, bh[nt]);
                }
            }
        }

        if (kt + 1 < KT) stage_store(cur ^ 1, va0, va1, vb0, vb1);
        __syncthreads();
    }

    // Epilogue (round 4 + optional silu(G)*acc fusion)
#pragma unroll
    for (int mt = 0; mt < 4; mt++) {
        const int r0 = m0 + mb + mt * 16 + g;
        const int r1 = r0 + 8;
        float* Crow0 = nullptr; float* Crow1 = nullptr;
        const float* Grow0 = nullptr; const float* Grow1 = nullptr;
        float s0 = 1.0f, s1 = 1.0f;
        if (r0 < m_rows) {
            size_t ro;
            if (MODE == 0) ro = (size_t)r0 * N;
            else {
                const int p = rowlist[r0];
                ro = (size_t)p * N;
                if (MODE == 2) s0 = g_pw[p];
            }
            Crow0 = C + ro;
            if (FUSE) Grow0 = G + ro;
        }
        if (r1 < m_rows) {
            size_t ro;
            if (MODE == 0) ro = (size_t)r1 * N;
            else {
                const int p = rowlist[r1];
                ro = (size_t)p * N;
                if (MODE == 2) s1 = g_pw[p];
            }
            Crow1 = C + ro;
            if (FUSE) Grow1 = G + ro;
        }
#pragma unroll
        for (int nt = 0; nt < 4; nt++) {
            const int c = n0 + nb + nt * 8 + 2 * t4;
            if (Crow0) {
                float o0 = acc[mt][nt][0] * s0, o1 = acc[mt][nt][1] * s0;
                if (FUSE) {
                    float2 gv = *(const float2*)(Grow0 + c);
                    o0 *= gv.x / (1.0f + expf(-gv.x));
                    o1 *= gv.y / (1.0f + expf(-gv.y));
                }
                *(float2*)(Crow0 + c) = make_float2(o0, o1);
            }
            if (Crow1) {
                float o0 = acc[mt][nt][2] * s1, o1 = acc[mt][nt][3] * s1;
                if (FUSE) {
                    float2 gv = *(const float2*)(Grow1 + c);
                    o0 *= gv.x / (1.0f + expf(-gv.x));
                    o1 *= gv.y / (1.0f + expf(-gv.y));
                }
                *(float2*)(Crow1 + c) = make_float2(o0, o1);
            }
        }
    }
}

// ---------------------------------------------------------------------------
// Final: out[t] += routed[2t] + routed[2t+1]
// ---------------------------------------------------------------------------
__global__ void final_add_kernel(float* __restrict__ out) {
    int i = blockIdx.x * blockDim.x + threadIdx.x;
    if (i >= T_TOK * HID / 4) return;
    const int t  = i >> 8;
    const int d4 = i & 255;
    float4 o = ((const float4*)out)[i];
    float4 a = ((const float4*)(g_routed + (size_t)(2 * t) * HID))[d4];
    float4 b = ((const float4*)(g_routed + (size_t)(2 * t + 1) * HID))[d4];
    o.x += a.x + b.x;
    o.y += a.y + b.y;
    o.z += a.z + b.z;
    o.w += a.w + b.w;
    ((float4*)out)[i] = o;
}

// ---------------------------------------------------------------------------
// Launch
// ---------------------------------------------------------------------------
extern "C" void kernel_launch(void* const* d_in, const int* in_sizes, int n_in,
                              void* d_out, int out_size) {
    const float* x  = (const float*)d_in[0];
    const float* rw = (const float*)d_in[1];
    const float* eg = (const float*)d_in[2];
    const float* eu = (const float*)d_in[3];
    const float* ed = (const float*)d_in[4];
    const float* sg = (const float*)d_in[5];
    const float* su = (const float*)d_in[6];
    const float* sd = (const float*)d_in[7];
    float* out = (float*)d_out;

    void *p_gate_s, *p_gate_r, *p_routed;
    cudaGetSymbolAddress(&p_gate_s, g_gate_s);
    cudaGetSymbolAddress(&p_gate_r, g_gate_r);
    cudaGetSymbolAddress(&p_routed, g_routed);

    cudaFuncSetAttribute(tgemm_kernel<0, 0>,
                         cudaFuncAttributeMaxDynamicSharedMemorySize, SMEM_DYN);
    cudaFuncSetAttribute(tgemm_kernel<0, 1>,
                         cudaFuncAttributeMaxDynamicSharedMemorySize, SMEM_DYN);
    cudaFuncSetAttribute(tgemm_kernel<1, 0>,
                         cudaFuncAttributeMaxDynamicSharedMemorySize, SMEM_DYN);
    cudaFuncSetAttribute(tgemm_kernel<1, 1>,
                         cudaFuncAttributeMaxDynamicSharedMemorySize, SMEM_DYN);
    cudaFuncSetAttribute(tgemm_kernel<2, 0>,
                         cudaFuncAttributeMaxDynamicSharedMemorySize, SMEM_DYN);

    zero_counts_kernel<<<1, 32>>>();
    router_kernel<<<T_TOK / 4, 128>>>(x, rw);

    // Shared expert: gate -> (up, silu fused) -> down
    tgemm_kernel<0, 0><<<dim3(FS / BN, T_TOK / BM, 1), 256, SMEM_DYN>>>(
        x, sg, (float*)p_gate_s, nullptr, T_TOK, FS, HID);
    tgemm_kernel<0, 1><<<dim3(FS / BN, T_TOK / BM, 1), 256, SMEM_DYN>>>(
        x, su, (float*)p_gate_s, (const float*)p_gate_s, T_TOK, FS, HID);
    tgemm_kernel<0, 0><<<dim3(HID / BN, T_TOK / BM, 1), 256, SMEM_DYN>>>(
        (const float*)p_gate_s, sd, out, nullptr, T_TOK, HID, FS);

    // Routed experts: gate -> (up, silu fused) -> down (scaled scatter)
    tgemm_kernel<1, 0><<<dim3(FE / BN, T_TOK / BM, NE), 256, SMEM_DYN>>>(
        x, eg, (float*)p_gate_r, nullptr, 0, FE, HID);
    tgemm_kernel<1, 1><<<dim3(FE / BN, T_TOK / BM, NE), 256, SMEM_DYN>>>(
        x, eu, (float*)p_gate_r, (const float*)p_gate_r, 0, FE, HID);
    tgemm_kernel<2, 0><<<dim3(HID / BN, T_TOK / BM, NE), 256, SMEM_DYN>>>(
        (const float*)p_gate_r, ed, (float*)p_routed, nullptr, 0, HID, FE);

    final_add_kernel<<<(T_TOK * HID / 4) / 256, 256>>>(out);
}